// round 8
// baseline (speedup 1.0000x reference)
#include <cuda_runtime.h>
#include <math.h>

#define V_MAX   100000
#define E_MAX   1600000
#define IN_CH   128
#define HEADS   4
#define HC      64
#define NEG_SLOPE 0.2f
#define SCAN_BLK 256

// ---------------- scratch (device globals; no allocation) ----------------
__device__ float g_z[(size_t)V_MAX * HC];     // projected features  [V,64]
__device__ float g_esrc[V_MAX * HEADS];       // per-node src logits [V,4]
__device__ float g_edst[V_MAX * HEADS];       // per-node dst logits [V,4]
__device__ int   g_deg[V_MAX];                // in-degree per node
__device__ int   g_excl[V_MAX];               // block-local exclusive scan
__device__ int   g_bsums[512];                // per-block sums
__device__ int   g_rowstart[V_MAX];           // CSR row offsets
__device__ int   g_cursor[V_MAX];             // scatter cursors
__device__ int   g_csr_src[E_MAX];            // src node per CSR slot

// ---------------- CSR build ----------------
__global__ void zero_deg_kernel(int v) {
    int i = blockIdx.x * blockDim.x + threadIdx.x;
    if (i < v) g_deg[i] = 0;
}

__global__ void count_kernel(const int* __restrict__ ei, int ecnt) {
    int e = blockIdx.x * blockDim.x + threadIdx.x;
    if (e < ecnt) atomicAdd(&g_deg[ei[ecnt + e]], 1);
}

__global__ void scan1_kernel(int v) {
    __shared__ int sh[SCAN_BLK];
    int t = threadIdx.x;
    int i = blockIdx.x * SCAN_BLK + t;
    int val = (i < v) ? g_deg[i] : 0;
    sh[t] = val;
    __syncthreads();
#pragma unroll
    for (int off = 1; off < SCAN_BLK; off <<= 1) {
        int y = (t >= off) ? sh[t - off] : 0;
        __syncthreads();
        sh[t] += y;
        __syncthreads();
    }
    if (i < v) g_excl[i] = sh[t] - val;
    if (t == SCAN_BLK - 1) g_bsums[blockIdx.x] = sh[t];
}

// Fused block-offset + rowstart: each block reduces bsums[0..b-1] in smem.
__global__ void scan3_kernel(int v) {
    __shared__ int red[SCAN_BLK];
    const int b = blockIdx.x;
    const int t = threadIdx.x;
    int sum = 0;
    for (int i = t; i < b; i += SCAN_BLK) sum += g_bsums[i];
    red[t] = sum;
    __syncthreads();
#pragma unroll
    for (int off = SCAN_BLK / 2; off; off >>= 1) {
        if (t < off) red[t] += red[t + off];
        __syncthreads();
    }
    int prefix = red[0];
    int i = b * SCAN_BLK + t;
    if (i < v) {
        int r = g_excl[i] + prefix;
        g_rowstart[i] = r;
        g_cursor[i]   = r;
    }
}

__global__ void scatter_kernel(const int* __restrict__ ei, int ecnt) {
    int e = blockIdx.x * blockDim.x + threadIdx.x;
    if (e >= ecnt) return;
    int s = ei[e];
    int d = ei[ecnt + e];
    int pos = atomicAdd(&g_cursor[d], 1);
    g_csr_src[pos] = s;
}

// ---------------- fused GEMM + logits (k-blocked, fewer LDS) -------------
// Per 4 k's: 4 LDS.128 broadcast x-loads + 4 LDS.128 w-loads feed 64 FMAs
// (vs 20 LDS before) — targets the measured L1=60% bottleneck.
__global__ void gemm_logits_kernel(const float* __restrict__ x,
                                   const float* __restrict__ W,
                                   const float* __restrict__ a_src,
                                   const float* __restrict__ a_dst,
                                   int v)
{
    extern __shared__ float sm[];
    float* Ws = sm;
    float* xs = Ws + IN_CH * HC;
    float* as = xs + 64 * 132;
    float* ad = as + 64;

    const int tx = threadIdx.x, ty = threadIdx.y;
    const int tid = ty * 16 + tx;
    const int row0 = blockIdx.x * 64;

    for (int i = tid; i < (IN_CH * HC) / 4; i += 256)
        ((float4*)Ws)[i] = ((const float4*)W)[i];
    if (tid < 64)       as[tid]      = a_src[tid];
    else if (tid < 128) ad[tid - 64] = a_dst[tid - 64];

    for (int i = tid; i < 64 * 32; i += 256) {
        int r = i >> 5, c4 = i & 31;
        float4 val = make_float4(0.f, 0.f, 0.f, 0.f);
        if (row0 + r < v)
            val = ((const float4*)x)[(size_t)(row0 + r) * 32 + c4];
        *(float4*)&xs[r * 132 + c4 * 4] = val;
    }
    __syncthreads();

    float acc[4][4];
#pragma unroll
    for (int i = 0; i < 4; ++i)
#pragma unroll
        for (int j = 0; j < 4; ++j) acc[i][j] = 0.f;

#pragma unroll 4
    for (int k0 = 0; k0 < IN_CH; k0 += 4) {
        float4 xv[4];
#pragma unroll
        for (int i = 0; i < 4; ++i)
            xv[i] = *(const float4*)&xs[(ty * 4 + i) * 132 + k0];
#pragma unroll
        for (int kk = 0; kk < 4; ++kk) {
            float4 wv = ((float4*)Ws)[(k0 + kk) * 16 + tx];
            float xk;
#pragma unroll
            for (int i = 0; i < 4; ++i) {
                xk = kk == 0 ? xv[i].x : kk == 1 ? xv[i].y : kk == 2 ? xv[i].z : xv[i].w;
                acc[i][0] += xk * wv.x;
                acc[i][1] += xk * wv.y;
                acc[i][2] += xk * wv.z;
                acc[i][3] += xk * wv.w;
            }
        }
    }

    const int h  = tx >> 2;
    const int c0 = (tx & 3) * 4;
#pragma unroll
    for (int i = 0; i < 4; ++i) {
        int row = row0 + ty * 4 + i;
        float ps = acc[i][0] * as[h * 16 + c0 + 0] + acc[i][1] * as[h * 16 + c0 + 1]
                 + acc[i][2] * as[h * 16 + c0 + 2] + acc[i][3] * as[h * 16 + c0 + 3];
        float pd = acc[i][0] * ad[h * 16 + c0 + 0] + acc[i][1] * ad[h * 16 + c0 + 1]
                 + acc[i][2] * ad[h * 16 + c0 + 2] + acc[i][3] * ad[h * 16 + c0 + 3];
        ps += __shfl_xor_sync(0xffffffffu, ps, 1);
        ps += __shfl_xor_sync(0xffffffffu, ps, 2);
        pd += __shfl_xor_sync(0xffffffffu, pd, 1);
        pd += __shfl_xor_sync(0xffffffffu, pd, 2);

        if (row < v) {
            *(float4*)&g_z[(size_t)row * HC + tx * 4] =
                make_float4(acc[i][0], acc[i][1], acc[i][2], acc[i][3]);
            if ((tx & 3) == 0) {
                g_esrc[row * HEADS + h] = ps;
                g_edst[row * HEADS + h] = pd;
            }
        }
    }
}

// ---------------- fused softmax + aggregation (CSR, smem-staged) ----------
__global__ void node_agg_kernel(float* __restrict__ out, int v) {
    __shared__ int   sh_s[8][32];
    __shared__ float sh_a[8][32][4];

    const int wid  = threadIdx.x >> 5;
    const int lane = threadIdx.x & 31;
    const int n = blockIdx.x * 8 + wid;
    if (n >= v) return;

    const int start = g_rowstart[n];
    const int degn  = g_deg[n];
    const float4 ed = *(const float4*)&g_edst[n * 4];
    const int head  = lane >> 3;

    float acc0 = 0.f, acc1 = 0.f;
    float d0 = 0.f, d1 = 0.f, d2 = 0.f, d3 = 0.f;

    for (int i0 = 0; i0 < degn; i0 += 32) {
        int idx = i0 + lane;
        int s = 0;
        float ex0 = 0.f, ex1 = 0.f, ex2 = 0.f, ex3 = 0.f;
        if (idx < degn) {
            s = __ldg(&g_csr_src[start + idx]);
            float4 es = *(const float4*)&g_esrc[s * 4];
            float w;
            w = es.x + ed.x; w = w > 0.f ? w : NEG_SLOPE * w; ex0 = __expf(w);
            w = es.y + ed.y; w = w > 0.f ? w : NEG_SLOPE * w; ex1 = __expf(w);
            w = es.z + ed.z; w = w > 0.f ? w : NEG_SLOPE * w; ex2 = __expf(w);
            w = es.w + ed.w; w = w > 0.f ? w : NEG_SLOPE * w; ex3 = __expf(w);
        }
        d0 += ex0; d1 += ex1; d2 += ex2; d3 += ex3;
        sh_s[wid][lane] = s;
        *(float4*)&sh_a[wid][lane][0] = make_float4(ex0, ex1, ex2, ex3);
        __syncwarp();

        int cnt = degn - i0; if (cnt > 32) cnt = 32;
        const float* zb = g_z + (size_t)lane * 2;
        int j = 0;
        for (; j + 8 <= cnt; j += 8) {
            int    sj[8];
            float2 zj[8];
            float  aj[8];
#pragma unroll
            for (int u = 0; u < 8; ++u) sj[u] = sh_s[wid][j + u];
#pragma unroll
            for (int u = 0; u < 8; ++u) zj[u] = *(const float2*)(zb + (size_t)sj[u] * HC);
#pragma unroll
            for (int u = 0; u < 8; ++u) aj[u] = sh_a[wid][j + u][head];
#pragma unroll
            for (int u = 0; u < 8; ++u) {
                acc0 += zj[u].x * aj[u];
                acc1 += zj[u].y * aj[u];
            }
        }
        for (; j < cnt; ++j) {
            int sj = sh_s[wid][j];
            float a = sh_a[wid][j][head];
            float2 zv = *(const float2*)(zb + (size_t)sj * HC);
            acc0 += zv.x * a; acc1 += zv.y * a;
        }
        __syncwarp();
    }

#pragma unroll
    for (int o = 16; o; o >>= 1) {
        d0 += __shfl_xor_sync(0xffffffffu, d0, o);
        d1 += __shfl_xor_sync(0xffffffffu, d1, o);
        d2 += __shfl_xor_sync(0xffffffffu, d2, o);
        d3 += __shfl_xor_sync(0xffffffffu, d3, o);
    }
    float den = head == 0 ? d0 : head == 1 ? d1 : head == 2 ? d2 : d3;
    float r = __frcp_rn(den + 1e-9f);
    acc0 *= r; acc1 *= r;
    acc0 = acc0 > 0.f ? acc0 : expm1f(acc0);
    acc1 = acc1 > 0.f ? acc1 : expm1f(acc1);
    *(float2*)&out[(size_t)n * HC + lane * 2] = make_float2(acc0, acc1);
}

// ---------------- launch ----------------
// gemm stays launch #4 so ncu keeps profiling it.
extern "C" void kernel_launch(void* const* d_in, const int* in_sizes, int n_in,
                              void* d_out, int out_size) {
    const float* x     = (const float*)d_in[0];
    const int*   ei    = (const int*)d_in[1];
    const float* W     = (const float*)d_in[2];
    const float* a_src = (const float*)d_in[3];
    const float* a_dst = (const float*)d_in[4];
    float* out = (float*)d_out;

    int v    = in_sizes[0] / IN_CH;
    int ecnt = in_sizes[1] / 2;
    int nb   = (v + SCAN_BLK - 1) / SCAN_BLK;

    const int smem = (IN_CH * HC + 64 * 132 + 128) * sizeof(float);
    cudaFuncSetAttribute(gemm_logits_kernel,
                         cudaFuncAttributeMaxDynamicSharedMemorySize, smem);

    zero_deg_kernel<<<(v + 255) / 256, 256>>>(v);
    count_kernel<<<(ecnt + 255) / 256, 256>>>(ei, ecnt);
    scan1_kernel<<<nb, SCAN_BLK>>>(v);
    gemm_logits_kernel<<<(v + 63) / 64, dim3(16, 16), smem>>>(x, W, a_src, a_dst, v);
    scan3_kernel<<<nb, SCAN_BLK>>>(v);
    scatter_kernel<<<(ecnt + 255) / 256, 256>>>(ei, ecnt);
    node_agg_kernel<<<(v + 7) / 8, 256>>>(out, v);
}